// round 5
// baseline (speedup 1.0000x reference)
#include <cuda_runtime.h>

#define N_HALF 4096
#define TWO_N  8192
#define D      8
#define NT     16                    // row/col tiles of 512
#define RT     512
#define BT     128                   // threads per block
#define ROWS_PT 4                    // rows per thread (RT = 4*BT)
#define CSPLIT 8                     // column octants per tile
#define CT     64                    // columns per block
#define NSLOT  (NT * CSPLIT)         // 128 partial slots per row
#define NPAIR  (NT * (NT + 1) / 2)   // 136 tile pairs
#define NBLK   (NPAIR * CSPLIT)      // 1088 blocks

#define LN2_F          0.6931471805599453f
#define HALF_LN2SQ_F   0.24022650695910072f   // ln2^2 / 2
#define HALF_LN2_F     0.34657359027997264f   // ln2 / 2
#define BOUNDARY_F     0.99999f

// __device__ scratch (allocation-free rule)
__device__ float g_denom[NSLOT * TWO_N];   // 4 MB partials (all slots written every run)
__device__ float g_partial[256];

typedef unsigned long long u64;

__device__ __forceinline__ float fast_sqrt(float x) { float y; asm("sqrt.approx.f32 %0, %1;" : "=f"(y) : "f"(x)); return y; }
__device__ __forceinline__ float fast_lg2(float x)  { float y; asm("lg2.approx.f32 %0, %1;"  : "=f"(y) : "f"(x)); return y; }
__device__ __forceinline__ float fast_rcp(float x)  { float y; asm("rcp.approx.f32 %0, %1;"  : "=f"(y) : "f"(x)); return y; }
__device__ __forceinline__ float fast_ex2(float x)  { float y; asm("ex2.approx.f32 %0, %1;"  : "=f"(y) : "f"(x)); return y; }

__device__ __forceinline__ u64 pack2(float lo, float hi) {
    u64 r; asm("mov.b64 %0, {%1,%2};" : "=l"(r) : "f"(lo), "f"(hi)); return r;
}
__device__ __forceinline__ u64 fma2(u64 a, u64 b, u64 c) {
    u64 r; asm("fma.rn.f32x2 %0, %1, %2, %3;" : "=l"(r) : "l"(a), "l"(b), "l"(c)); return r;
}

// ---- shared building blocks (identical in pair + fin1: bit-exact self-term)
__device__ __forceinline__ void load_point(const float* __restrict__ zi,
                                           const float* __restrict__ zj,
                                           int i, float4& a, float4& b) {
    const float* src = (i < N_HALF) ? (zi + (size_t)i * D)
                                    : (zj + (size_t)(i - N_HALF) * D);
    a = *reinterpret_cast<const float4*>(src);
    b = *reinterpret_cast<const float4*>(src + 4);
}

__device__ __forceinline__ float raw8(const float4& a, const float4& b) {
    float d = __fmul_rn(a.x, a.x);
    d = fmaf(a.y, a.y, d); d = fmaf(a.z, a.z, d); d = fmaf(a.w, a.w, d);
    d = fmaf(b.x, b.x, d); d = fmaf(b.y, b.y, d); d = fmaf(b.z, b.z, d);
    d = fmaf(b.w, b.w, d);
    return d;
}

// row-side augmented vector: a = [-4*inv*z(8); 2*inv*raw; 2*inv]
__device__ __forceinline__ void build_a(const float4& a, const float4& b, u64 A[5]) {
    float raw = raw8(a, b);
    float inv = 1.0f / (1.0f - fminf(raw, BOUNDARY_F));
    float m   = __fmul_rn(-4.0f, inv);
    A[0] = pack2(__fmul_rn(m, a.x), __fmul_rn(m, a.y));
    A[1] = pack2(__fmul_rn(m, a.z), __fmul_rn(m, a.w));
    A[2] = pack2(__fmul_rn(m, b.x), __fmul_rn(m, b.y));
    A[3] = pack2(__fmul_rn(m, b.z), __fmul_rn(m, b.w));
    float i2 = __fadd_rn(inv, inv);
    A[4] = pack2(__fmul_rn(i2, raw), i2);
}

// col-side augmented vector: b = [inv*z(8); inv; inv*raw]
__device__ __forceinline__ void build_b(const float4& a, const float4& b, u64 B[5]) {
    float raw = raw8(a, b);
    float inv = 1.0f / (1.0f - fminf(raw, BOUNDARY_F));
    B[0] = pack2(__fmul_rn(inv, a.x), __fmul_rn(inv, a.y));
    B[1] = pack2(__fmul_rn(inv, a.z), __fmul_rn(inv, a.w));
    B[2] = pack2(__fmul_rn(inv, b.x), __fmul_rn(inv, b.y));
    B[3] = pack2(__fmul_rn(inv, b.z), __fmul_rn(inv, b.w));
    B[4] = pack2(inv, __fmul_rn(inv, raw));
}

// x = max(1 + a.b, 1)
__device__ __forceinline__ float dot10_x(const u64 A[5], const u64 B[5]) {
    u64 s = fma2(A[4], B[4], pack2(1.0f, 0.0f));
    s = fma2(A[0], B[0], s);
    s = fma2(A[1], B[1], s);
    s = fma2(A[2], B[2], s);
    s = fma2(A[3], B[3], s);
    float lo, hi;
    asm("mov.b64 {%0,%1}, %2;" : "=f"(lo), "=f"(hi) : "l"(s));
    return fmaxf(__fadd_rn(lo, hi), 1.0f);
}

// e = exp(2*sim) = ex2( 1 / ((1 + arcosh(x)) * ln2/2) )
__device__ __forceinline__ float chain_e(float x) {
    float x2 = fmaf(x, x, -1.0f);                  // >= 0 since x >= 1
    float s  = fast_sqrt(x2);
    float l  = fast_lg2(__fadd_rn(x, s));
    float dn = fmaf(l, HALF_LN2SQ_F, HALF_LN2_F);
    return fast_ex2(fast_rcp(dn));
}
// sim = 1/(1+arcosh(x))  (finalize only)
__device__ __forceinline__ float chain_sim(float x) {
    float x2 = fmaf(x, x, -1.0f);
    float s  = fast_sqrt(x2);
    float l  = fast_lg2(__fadd_rn(x, s));
    return fast_rcp(fmaf(l, LN2_F, 1.0f));
}

// ---------------------------------------------------------------------------
// Kernel 0: empty (launch-index alignment so ncu -s 5 lands on pair_kernel)
// ---------------------------------------------------------------------------
__global__ void dummy_kernel() {}

// ---------------------------------------------------------------------------
// Kernel 1: symmetric pairwise tiles -> partial softmax denominators
// grid = 1088, block = 128 (4 rows/thread, 64 columns/block)
// ---------------------------------------------------------------------------
__global__ void __launch_bounds__(BT)
pair_kernel(const float* __restrict__ zi, const float* __restrict__ zj) {
    __shared__ u64   sb[5][CT];     // column augmented vectors (SoA)
    __shared__ float wacc[4][CT];   // per-warp column sums

    const int t    = threadIdx.x;
    const int lane = t & 31;
    const int w    = t >> 5;
    const int nxt  = (lane + 1) & 31;

    // decode (a, b, h)
    int p = blockIdx.x >> 3;
    int h = blockIdx.x & 7;
    int a = 0, rem = p;
    while (rem >= NT - a) { rem -= NT - a; ++a; }
    int b = a + rem;
    const bool diag = (a == b);
    const int jbase = b * RT + h * CT;

    // stage 64 columns
    if (t < CT) {
        float4 ca, cb;
        load_point(zi, zj, jbase + t, ca, cb);
        u64 B[5];
        build_b(ca, cb, B);
        sb[0][t] = B[0]; sb[1][t] = B[1]; sb[2][t] = B[2];
        sb[3][t] = B[3]; sb[4][t] = B[4];
    }

    // build 4 row vectors
    u64 A[ROWS_PT][5];
    #pragma unroll
    for (int r = 0; r < ROWS_PT; ++r) {
        float4 ra, rb;
        load_point(zi, zj, a * RT + r * BT + t, ra, rb);
        build_a(ra, rb, A[r]);
    }

    __syncthreads();

    float racc[ROWS_PT] = {0.f, 0.f, 0.f, 0.f};

    if (diag) {
        #pragma unroll 4
        for (int c = 0; c < CT; ++c) {                    // broadcast LDS
            u64 B[5] = { sb[0][c], sb[1][c], sb[2][c], sb[3][c], sb[4][c] };
            #pragma unroll
            for (int r = 0; r < ROWS_PT; ++r)
                racc[r] += chain_e(dot10_x(A[r], B));
        }
    } else {
        #pragma unroll
        for (int g = 0; g < CT / 32; ++g) {
            float cacc = 0.0f;                            // systolic ring acc
            #pragma unroll 4
            for (int k = 0; k < 32; ++k) {
                int c = (g << 5) + ((lane + k) & 31);     // conflict-free
                u64 B[5] = { sb[0][c], sb[1][c], sb[2][c], sb[3][c], sb[4][c] };
                float e0 = chain_e(dot10_x(A[0], B));
                float e1 = chain_e(dot10_x(A[1], B));
                float e2 = chain_e(dot10_x(A[2], B));
                float e3 = chain_e(dot10_x(A[3], B));
                racc[0] += e0; racc[1] += e1; racc[2] += e2; racc[3] += e3;
                cacc += ((e0 + e1) + (e2 + e3));
                cacc = __shfl_sync(0xFFFFFFFFu, cacc, nxt, 32);
            }
            wacc[w][(g << 5) + lane] = cacc;              // lane holds col 'lane'
        }
    }

    // row-side partials: slot (b, h)
    const size_t rbase = (size_t)(b * CSPLIT + h) * TWO_N + a * RT + t;
    #pragma unroll
    for (int r = 0; r < ROWS_PT; ++r)
        g_denom[rbase + (size_t)r * BT] = racc[r];

    // column-side partials: slot (a, h)
    if (!diag) {
        __syncthreads();
        if (t < CT) {
            float c = ((wacc[0][t] + wacc[1][t]) + (wacc[2][t] + wacc[3][t]));
            g_denom[(size_t)(a * CSPLIT + h) * TWO_N + jbase + t] = c;
        }
    }
}

// ---------------------------------------------------------------------------
// Kernel 2: denom combine (8 threads/row x 16 slots) + positives -> 256 partials
// grid = 256, block = 256 (32 rows per block)
// ---------------------------------------------------------------------------
__global__ void __launch_bounds__(256)
fin1_kernel(const float* __restrict__ zi, const float* __restrict__ zj) {
    __shared__ float sacc[8][32];
    const int t = threadIdx.x;
    const int r = t & 31;          // row within block
    const int g = t >> 5;          // slot group (16 slots each)
    const int i = blockIdx.x * 32 + r;

    float d = 0.0f;
    #pragma unroll
    for (int c = 0; c < 16; ++c)
        d += g_denom[(size_t)(g * 16 + c) * TWO_N + i];
    sacc[g][r] = d;
    __syncthreads();

    if (g == 0) {                  // warp 0 finishes the 32 rows
        float denom = 0.0f;
        #pragma unroll
        for (int ww = 0; ww < 8; ++ww) denom += sacc[ww][r];

        float4 ua, ub;
        load_point(zi, zj, i, ua, ub);
        u64 Ai[5], Bi[5];
        build_a(ua, ub, Ai);
        build_b(ua, ub, Bi);
        denom -= chain_e(dot10_x(Ai, Bi));        // bit-exact self cancel

        const int pp = (i < N_HALF) ? (i + N_HALF) : (i - N_HALF);
        float4 va, vb;
        load_point(zi, zj, pp, va, vb);
        u64 Bp[5];
        build_b(va, vb, Bp);
        float sim = chain_sim(dot10_x(Ai, Bp));

        float loss = fast_lg2(denom) * LN2_F - 2.0f * sim;
        #pragma unroll
        for (int s = 16; s > 0; s >>= 1)
            loss += __shfl_xor_sync(0xFFFFFFFFu, loss, s);
        if (r == 0) g_partial[blockIdx.x] = loss;
    }
}

// ---------------------------------------------------------------------------
// Kernel 3: reduce 256 partials
// ---------------------------------------------------------------------------
__global__ void __launch_bounds__(256)
fin2_kernel(float* __restrict__ out) {
    __shared__ float red[256];
    const int t = threadIdx.x;
    red[t] = g_partial[t];
    __syncthreads();
    #pragma unroll
    for (int s = 128; s > 0; s >>= 1) {
        if (t < s) red[t] += red[t + s];
        __syncthreads();
    }
    if (t == 0) out[0] = red[0] / (float)TWO_N;
}

// ---------------------------------------------------------------------------
extern "C" void kernel_launch(void* const* d_in, const int* in_sizes, int n_in,
                              void* d_out, int out_size) {
    const float* zi = (const float*)d_in[0];
    const float* zj = (const float*)d_in[1];
    float* out = (float*)d_out;

    dummy_kernel<<<1, 32>>>();                 // aligns ncu -s 5 onto pair_kernel
    pair_kernel<<<NBLK, BT>>>(zi, zj);
    fin1_kernel<<<256, 256>>>(zi, zj);
    fin2_kernel<<<1, 256>>>(out);
}

// round 6
// speedup vs baseline: 1.1007x; 1.1007x over previous
#include <cuda_runtime.h>

#define N_HALF 4096
#define TWO_N  8192
#define D      8
#define NT     16                    // row/col tiles of 512
#define RT     512
#define BT     128                   // threads per block
#define ROWS_PT 4                    // rows per thread (RT = 4*BT)
#define CSPLIT 8                     // column octants per tile
#define CT     64                    // columns per block
#define NSLOT  (NT * CSPLIT)         // 128 partial slots per row
#define NPAIR  (NT * (NT + 1) / 2)   // 136 tile pairs
#define NBLK   (NPAIR * CSPLIT)      // 1088 blocks

#define LN2_F          0.6931471805599453f
#define HALF_LN2SQ_F   0.24022650695910072f   // ln2^2 / 2
#define HALF_LN2_F     0.34657359027997264f   // ln2 / 2
#define BOUNDARY_F     0.99999f

// __device__ scratch (allocation-free rule)
__device__ float        g_denom[NSLOT * TWO_N];   // 4 MB partials
__device__ float        g_partial[256];
__device__ unsigned int g_cnt;                     // zero-init at load

typedef unsigned long long u64;

__device__ __forceinline__ float fast_sqrt(float x) { float y; asm("sqrt.approx.f32 %0, %1;" : "=f"(y) : "f"(x)); return y; }
__device__ __forceinline__ float fast_lg2(float x)  { float y; asm("lg2.approx.f32 %0, %1;"  : "=f"(y) : "f"(x)); return y; }
__device__ __forceinline__ float fast_ex2(float x)  { float y; asm("ex2.approx.f32 %0, %1;"  : "=f"(y) : "f"(x)); return y; }

// Reciprocal WITHOUT the MUFU pipe: exponent bit-trick seed + 2 Newton steps.
// d is always a positive normal in [~0.3, ~7]; rel err after 2 steps ~1e-6.
__device__ __forceinline__ float rcp_alu(float d) {
    float y = __int_as_float(0x7EF311C3 - __float_as_int(d));   // ~5% seed
    y = __fmul_rn(y, fmaf(-d, y, 2.0f));                        // ~0.25%
    y = __fmul_rn(y, fmaf(-d, y, 2.0f));                        // ~6e-6
    return y;
}

__device__ __forceinline__ u64 pack2(float lo, float hi) {
    u64 r; asm("mov.b64 %0, {%1,%2};" : "=l"(r) : "f"(lo), "f"(hi)); return r;
}
__device__ __forceinline__ u64 fma2(u64 a, u64 b, u64 c) {
    u64 r; asm("fma.rn.f32x2 %0, %1, %2, %3;" : "=l"(r) : "l"(a), "l"(b), "l"(c)); return r;
}

// ---- shared building blocks (identical in both kernels: bit-exact self-term)
__device__ __forceinline__ void load_point(const float* __restrict__ zi,
                                           const float* __restrict__ zj,
                                           int i, float4& a, float4& b) {
    const float* src = (i < N_HALF) ? (zi + (size_t)i * D)
                                    : (zj + (size_t)(i - N_HALF) * D);
    a = *reinterpret_cast<const float4*>(src);
    b = *reinterpret_cast<const float4*>(src + 4);
}

__device__ __forceinline__ float raw8(const float4& a, const float4& b) {
    float d = __fmul_rn(a.x, a.x);
    d = fmaf(a.y, a.y, d); d = fmaf(a.z, a.z, d); d = fmaf(a.w, a.w, d);
    d = fmaf(b.x, b.x, d); d = fmaf(b.y, b.y, d); d = fmaf(b.z, b.z, d);
    d = fmaf(b.w, b.w, d);
    return d;
}

// row-side augmented vector: a = [-4*inv*z(8); 2*inv*raw; 2*inv]
__device__ __forceinline__ void build_a(const float4& a, const float4& b, u64 A[5]) {
    float raw = raw8(a, b);
    float inv = 1.0f / (1.0f - fminf(raw, BOUNDARY_F));   // precise; O(2N) only
    float m   = __fmul_rn(-4.0f, inv);
    A[0] = pack2(__fmul_rn(m, a.x), __fmul_rn(m, a.y));
    A[1] = pack2(__fmul_rn(m, a.z), __fmul_rn(m, a.w));
    A[2] = pack2(__fmul_rn(m, b.x), __fmul_rn(m, b.y));
    A[3] = pack2(__fmul_rn(m, b.z), __fmul_rn(m, b.w));
    float i2 = __fadd_rn(inv, inv);
    A[4] = pack2(__fmul_rn(i2, raw), i2);
}

// col-side augmented vector: b = [inv*z(8); inv; inv*raw]
__device__ __forceinline__ void build_b(const float4& a, const float4& b, u64 B[5]) {
    float raw = raw8(a, b);
    float inv = 1.0f / (1.0f - fminf(raw, BOUNDARY_F));
    B[0] = pack2(__fmul_rn(inv, a.x), __fmul_rn(inv, a.y));
    B[1] = pack2(__fmul_rn(inv, a.z), __fmul_rn(inv, a.w));
    B[2] = pack2(__fmul_rn(inv, b.x), __fmul_rn(inv, b.y));
    B[3] = pack2(__fmul_rn(inv, b.z), __fmul_rn(inv, b.w));
    B[4] = pack2(inv, __fmul_rn(inv, raw));
}

// x = max(1 + a.b, 1)
__device__ __forceinline__ float dot10_x(const u64 A[5], const u64 B[5]) {
    u64 s = fma2(A[4], B[4], pack2(1.0f, 0.0f));
    s = fma2(A[0], B[0], s);
    s = fma2(A[1], B[1], s);
    s = fma2(A[2], B[2], s);
    s = fma2(A[3], B[3], s);
    float lo, hi;
    asm("mov.b64 {%0,%1}, %2;" : "=f"(lo), "=f"(hi) : "l"(s));
    return fmaxf(__fadd_rn(lo, hi), 1.0f);
}

// e = exp(2*sim) = ex2( 1 / ((1 + arcosh(x)) * ln2/2) )   -- 3 MUFU + ALU rcp
__device__ __forceinline__ float chain_e(float x) {
    float x2 = fmaf(x, x, -1.0f);                  // >= 0 since x >= 1
    float s  = fast_sqrt(x2);                      // MUFU
    float l  = fast_lg2(__fadd_rn(x, s));          // MUFU
    float dn = fmaf(l, HALF_LN2SQ_F, HALF_LN2_F);  // (1+dist)*ln2/2, in [0.34,~2.4]
    return fast_ex2(rcp_alu(dn));                  // MUFU (rcp moved to ALU)
}
// sim = 1/(1+arcosh(x))  (finalize only; 2N evals)
__device__ __forceinline__ float chain_sim(float x) {
    float x2 = fmaf(x, x, -1.0f);
    float s  = fast_sqrt(x2);
    float l  = fast_lg2(__fadd_rn(x, s));
    return rcp_alu(fmaf(l, LN2_F, 1.0f));
}

// ---------------------------------------------------------------------------
// Kernel 1: symmetric pairwise tiles -> partial softmax denominators
// grid = 1088, block = 128 (4 rows/thread, 64 columns/block)
// ---------------------------------------------------------------------------
__global__ void __launch_bounds__(BT)
pair_kernel(const float* __restrict__ zi, const float* __restrict__ zj) {
    __shared__ u64   sb[5][CT];     // column augmented vectors (SoA)
    __shared__ float wacc[4][CT];   // per-warp column sums

    const int t    = threadIdx.x;
    const int lane = t & 31;
    const int w    = t >> 5;
    const int nxt  = (lane + 1) & 31;

    // decode (a, b, h)
    int p = blockIdx.x >> 3;
    int h = blockIdx.x & 7;
    int a = 0, rem = p;
    while (rem >= NT - a) { rem -= NT - a; ++a; }
    int b = a + rem;
    const bool diag = (a == b);
    const int jbase = b * RT + h * CT;

    // stage 64 columns
    if (t < CT) {
        float4 ca, cb;
        load_point(zi, zj, jbase + t, ca, cb);
        u64 B[5];
        build_b(ca, cb, B);
        sb[0][t] = B[0]; sb[1][t] = B[1]; sb[2][t] = B[2];
        sb[3][t] = B[3]; sb[4][t] = B[4];
    }

    // build 4 row vectors
    u64 A[ROWS_PT][5];
    #pragma unroll
    for (int r = 0; r < ROWS_PT; ++r) {
        float4 ra, rb;
        load_point(zi, zj, a * RT + r * BT + t, ra, rb);
        build_a(ra, rb, A[r]);
    }

    __syncthreads();

    float racc[ROWS_PT] = {0.f, 0.f, 0.f, 0.f};

    if (diag) {
        #pragma unroll 4
        for (int c = 0; c < CT; ++c) {                    // broadcast LDS
            u64 B[5] = { sb[0][c], sb[1][c], sb[2][c], sb[3][c], sb[4][c] };
            #pragma unroll
            for (int r = 0; r < ROWS_PT; ++r)
                racc[r] += chain_e(dot10_x(A[r], B));
        }
    } else {
        #pragma unroll
        for (int g = 0; g < CT / 32; ++g) {
            float cacc = 0.0f;                            // systolic ring acc
            #pragma unroll 4
            for (int k = 0; k < 32; ++k) {
                int c = (g << 5) + ((lane + k) & 31);     // conflict-free
                u64 B[5] = { sb[0][c], sb[1][c], sb[2][c], sb[3][c], sb[4][c] };
                float e0 = chain_e(dot10_x(A[0], B));
                float e1 = chain_e(dot10_x(A[1], B));
                float e2 = chain_e(dot10_x(A[2], B));
                float e3 = chain_e(dot10_x(A[3], B));
                racc[0] += e0; racc[1] += e1; racc[2] += e2; racc[3] += e3;
                cacc += ((e0 + e1) + (e2 + e3));
                cacc = __shfl_sync(0xFFFFFFFFu, cacc, nxt, 32);
            }
            wacc[w][(g << 5) + lane] = cacc;              // lane holds col 'lane'
        }
    }

    // row-side partials: slot (b, h)
    const size_t rbase = (size_t)(b * CSPLIT + h) * TWO_N + a * RT + t;
    #pragma unroll
    for (int r = 0; r < ROWS_PT; ++r)
        g_denom[rbase + (size_t)r * BT] = racc[r];

    // column-side partials: slot (a, h)
    if (!diag) {
        __syncthreads();
        if (t < CT) {
            float c = ((wacc[0][t] + wacc[1][t]) + (wacc[2][t] + wacc[3][t]));
            g_denom[(size_t)(a * CSPLIT + h) * TWO_N + jbase + t] = c;
        }
    }
}

// ---------------------------------------------------------------------------
// Kernel 2: denom combine (8 threads/row x 16 slots) + positives + full reduce
// grid = 256, block = 256 (32 rows per block); last block finalizes
// ---------------------------------------------------------------------------
__global__ void __launch_bounds__(256)
fin_kernel(const float* __restrict__ zi, const float* __restrict__ zj,
           float* __restrict__ out) {
    __shared__ float sacc[8][32];
    const int t = threadIdx.x;
    const int r = t & 31;          // row within block
    const int g = t >> 5;          // slot group (16 slots each)
    const int i = blockIdx.x * 32 + r;

    float d = 0.0f;
    #pragma unroll
    for (int c = 0; c < 16; ++c)
        d += g_denom[(size_t)(g * 16 + c) * TWO_N + i];
    sacc[g][r] = d;
    __syncthreads();

    if (g == 0) {                  // warp 0 finishes the 32 rows
        float denom = 0.0f;
        #pragma unroll
        for (int ww = 0; ww < 8; ++ww) denom += sacc[ww][r];

        float4 ua, ub;
        load_point(zi, zj, i, ua, ub);
        u64 Ai[5], Bi[5];
        build_a(ua, ub, Ai);
        build_b(ua, ub, Bi);
        denom -= chain_e(dot10_x(Ai, Bi));        // bit-exact self cancel

        const int pp = (i < N_HALF) ? (i + N_HALF) : (i - N_HALF);
        float4 va, vb;
        load_point(zi, zj, pp, va, vb);
        u64 Bp[5];
        build_b(va, vb, Bp);
        float sim = chain_sim(dot10_x(Ai, Bp));

        float loss = fast_lg2(denom) * LN2_F - 2.0f * sim;
        #pragma unroll
        for (int s = 16; s > 0; s >>= 1)
            loss += __shfl_xor_sync(0xFFFFFFFFu, loss, s);

        unsigned tk = 0u;
        if (r == 0) {
            g_partial[blockIdx.x] = loss;
            __threadfence();
            tk = atomicAdd(&g_cnt, 1u) + 1u;
        }
        tk = __shfl_sync(0xFFFFFFFFu, tk, 0);
        if (tk == 256u) {                          // last block finalizes
            __threadfence();
            float v = 0.0f;
            #pragma unroll
            for (int j = 0; j < 8; ++j) v += g_partial[r + j * 32];
            #pragma unroll
            for (int s = 16; s > 0; s >>= 1)
                v += __shfl_xor_sync(0xFFFFFFFFu, v, s);
            if (r == 0) {
                out[0] = v / (float)TWO_N;
                g_cnt = 0;                         // reset for next replay
            }
        }
    }
}

// ---------------------------------------------------------------------------
extern "C" void kernel_launch(void* const* d_in, const int* in_sizes, int n_in,
                              void* d_out, int out_size) {
    const float* zi = (const float*)d_in[0];
    const float* zj = (const float*)d_in[1];
    float* out = (float*)d_out;

    pair_kernel<<<NBLK, BT>>>(zi, zj);
    fin_kernel<<<256, 256>>>(zi, zj, out);
}